// round 1
// baseline (speedup 1.0000x reference)
#include <cuda_runtime.h>
#include <math.h>

#define BATCH   2
#define SEQ     2048
#define DMODEL  2048
#define NHEADS  16
#define DHEAD   128
#define MROWS   (BATCH*SEQ)   // 4096

// Scratch (allocation-free: __device__ globals)
__device__ float g_Q[BATCH*NHEADS*SEQ*DHEAD];   // [B][H][S][Dh]
__device__ float g_K[BATCH*NHEADS*SEQ*DHEAD];
__device__ float g_V[BATCH*NHEADS*SEQ*DHEAD];
__device__ float g_Z[BATCH*SEQ*NHEADS*DHEAD];   // [B][S][H][Dh] (contiguous K for out-proj)

// ---------------------------------------------------------------------------
// Phase 1: QKV projection.  grid = (16 heads, 32 m-tiles, 3 {Q,K,V})
// C[m][h*128+e] = X[m][:] . W_sel[h][:][e] + b_sel[h][e], written to [B][H][S][Dh]
// ---------------------------------------------------------------------------
__global__ __launch_bounds__(256) void qkv_gemm_kernel(
    const float* __restrict__ X,
    const float* __restrict__ Wq, const float* __restrict__ Wk, const float* __restrict__ Wv,
    const float* __restrict__ bq, const float* __restrict__ bk, const float* __restrict__ bv)
{
    __shared__ float As[16][132];   // A tile, transposed [k][m]
    __shared__ float Bs[16][132];   // B tile [k][n]

    const float* W; const float* bias; float* out;
    if (blockIdx.z == 0)      { W = Wq; bias = bq; out = g_Q; }
    else if (blockIdx.z == 1) { W = Wk; bias = bk; out = g_K; }
    else                      { W = Wv; bias = bv; out = g_V; }

    const int h   = blockIdx.x;
    const int m0  = blockIdx.y * 128;
    const int tid = threadIdx.x;
    const int txc = tid & 15, tyr = tid >> 4;
    const float* Wh = W + h * DMODEL * DHEAD;   // [2048][128] row-major

    float acc[8][8];
    #pragma unroll
    for (int i = 0; i < 8; i++)
        #pragma unroll
        for (int j = 0; j < 8; j++) acc[i][j] = 0.f;

    for (int k0 = 0; k0 < DMODEL; k0 += 16) {
        // A tile: 128 rows x 16 cols -> As[k][m]
        #pragma unroll
        for (int it = 0; it < 2; ++it) {
            int t  = tid + it * 256;
            int ar = t >> 2;           // 0..127
            int ac = (t & 3) * 4;      // 0,4,8,12
            float4 v = *(const float4*)(X + (m0 + ar) * DMODEL + k0 + ac);
            As[ac + 0][ar] = v.x; As[ac + 1][ar] = v.y;
            As[ac + 2][ar] = v.z; As[ac + 3][ar] = v.w;
        }
        // B tile: 16 rows x 128 cols
        #pragma unroll
        for (int it = 0; it < 2; ++it) {
            int t  = tid + it * 256;
            int br = t >> 5;           // 0..15
            int bc = (t & 31) * 4;
            *(float4*)&Bs[br][bc] = *(const float4*)(Wh + (k0 + br) * DHEAD + bc);
        }
        __syncthreads();

        #pragma unroll
        for (int k = 0; k < 16; k++) {
            float ra[8], rb[8];
            *(float4*)(ra)     = *(float4*)&As[k][tyr * 8];
            *(float4*)(ra + 4) = *(float4*)&As[k][tyr * 8 + 4];
            *(float4*)(rb)     = *(float4*)&Bs[k][txc * 8];
            *(float4*)(rb + 4) = *(float4*)&Bs[k][txc * 8 + 4];
            #pragma unroll
            for (int i = 0; i < 8; i++)
                #pragma unroll
                for (int j = 0; j < 8; j++)
                    acc[i][j] = fmaf(ra[i], rb[j], acc[i][j]);
        }
        __syncthreads();
    }

    #pragma unroll
    for (int i = 0; i < 8; i++) {
        int m = m0 + tyr * 8 + i;
        int b = m >> 11, s = m & 2047;
        float*       orow = out + ((b * NHEADS + h) * SEQ + s) * DHEAD + txc * 8;
        const float* brow = bias + h * DHEAD + txc * 8;
        #pragma unroll
        for (int j = 0; j < 8; j++) orow[j] = acc[i][j] + brow[j];
    }
}

// ---------------------------------------------------------------------------
// Phase 2: causal flash attention.  grid = (32 q-tiles, B*H)
// block: 256 threads (16x16), each thread: 4 S-rows x 4 S-cols, 4x8 O frag.
// smem: Qst[128][68] (transposed) | KV buffer (K transposed [128][68] then V [64][132]) | Ps[64][68]
// ---------------------------------------------------------------------------
#define ATTN_SMEM_FLOATS (128*68 + 128*68 + 64*68)
#define ATTN_SMEM_BYTES  (ATTN_SMEM_FLOATS * 4)

__global__ __launch_bounds__(256, 2) void attn_kernel()
{
    extern __shared__ float sm[];
    float* Qst = sm;                 // [128][68]  Qst[k*68+r]
    float* KV  = sm + 128 * 68;      // K: [128][68]  /  V: [64][132]
    float* Ps  = sm + 2 * 128 * 68;  // [64][68]

    const int tid = threadIdx.x;
    const int tx  = tid & 15, ty = tid >> 4;
    const int tx4 = tx * 4, ty4 = ty * 4, tx8 = tx * 8;
    const int bh  = blockIdx.y;
    const int b   = bh >> 4, h = bh & 15;
    const int q0  = blockIdx.x * 64;

    const float* Qg = g_Q + (size_t)(b * NHEADS + h) * SEQ * DHEAD;
    const float* Kg = g_K + (size_t)(b * NHEADS + h) * SEQ * DHEAD;
    const float* Vg = g_V + (size_t)(b * NHEADS + h) * SEQ * DHEAD;

    // Load Q tile (64 x 128) transposed into Qst[k][r]
    {
        int row = tid >> 5;            // 0..7
        int c4  = (tid & 31) * 4;      // 0..124
        #pragma unroll
        for (int it = 0; it < 8; ++it) {
            int r = row + it * 8;
            float4 v = *(const float4*)(Qg + (q0 + r) * DHEAD + c4);
            Qst[(c4 + 0) * 68 + r] = v.x;
            Qst[(c4 + 1) * 68 + r] = v.y;
            Qst[(c4 + 2) * 68 + r] = v.z;
            Qst[(c4 + 3) * 68 + r] = v.w;
        }
    }

    float m_i[4], l_i[4], acc[4][8];
    #pragma unroll
    for (int i = 0; i < 4; i++) {
        m_i[i] = -INFINITY; l_i[i] = 0.f;
        #pragma unroll
        for (int j = 0; j < 8; j++) acc[i][j] = 0.f;
    }

    const float scale = 0.08838834764831845f;   // 1/sqrt(128)
    const int ntiles = blockIdx.x + 1;           // causal: only tiles <= diag

    for (int kt = 0; kt < ntiles; ++kt) {
        const int k0t = kt * 64;
        __syncthreads();   // KV free (prev PV done); also orders Q store on first iter

        // Load K tile (64 x 128) transposed into KV[k][c]
        {
            int row = tid >> 5;
            int c4  = (tid & 31) * 4;
            #pragma unroll
            for (int it = 0; it < 8; ++it) {
                int r = row + it * 8;
                float4 v = *(const float4*)(Kg + (k0t + r) * DHEAD + c4);
                KV[(c4 + 0) * 68 + r] = v.x;
                KV[(c4 + 1) * 68 + r] = v.y;
                KV[(c4 + 2) * 68 + r] = v.z;
                KV[(c4 + 3) * 68 + r] = v.w;
            }
        }
        __syncthreads();

        // S = Q K^T  (4x4 frag per thread)
        float sa[4][4];
        #pragma unroll
        for (int i = 0; i < 4; i++)
            #pragma unroll
            for (int j = 0; j < 4; j++) sa[i][j] = 0.f;

        #pragma unroll 8
        for (int k = 0; k < 128; k++) {
            float4 qv = *(float4*)&Qst[k * 68 + ty4];
            float4 kv = *(float4*)&KV [k * 68 + tx4];
            float qa[4] = {qv.x, qv.y, qv.z, qv.w};
            float ka[4] = {kv.x, kv.y, kv.z, kv.w};
            #pragma unroll
            for (int i = 0; i < 4; i++)
                #pragma unroll
                for (int j = 0; j < 4; j++)
                    sa[i][j] = fmaf(qa[i], ka[j], sa[i][j]);
        }

        // scale + causal mask + online softmax
        #pragma unroll
        for (int i = 0; i < 4; i++) {
            const int qg = q0 + ty4 + i;
            float mx = -INFINITY;
            #pragma unroll
            for (int j = 0; j < 4; j++) {
                float sv = sa[i][j] * scale;
                if (k0t + tx4 + j > qg) sv = -1e5f;
                sa[i][j] = sv;
                mx = fmaxf(mx, sv);
            }
            mx = fmaxf(mx, __shfl_xor_sync(0xffffffffu, mx, 1, 16));
            mx = fmaxf(mx, __shfl_xor_sync(0xffffffffu, mx, 2, 16));
            mx = fmaxf(mx, __shfl_xor_sync(0xffffffffu, mx, 4, 16));
            mx = fmaxf(mx, __shfl_xor_sync(0xffffffffu, mx, 8, 16));
            float mnew = fmaxf(m_i[i], mx);
            float ef   = __expf(m_i[i] - mnew);
            m_i[i] = mnew;
            float rs = 0.f;
            #pragma unroll
            for (int j = 0; j < 4; j++) {
                float p = __expf(sa[i][j] - mnew);
                sa[i][j] = p;
                rs += p;
            }
            rs += __shfl_xor_sync(0xffffffffu, rs, 1, 16);
            rs += __shfl_xor_sync(0xffffffffu, rs, 2, 16);
            rs += __shfl_xor_sync(0xffffffffu, rs, 4, 16);
            rs += __shfl_xor_sync(0xffffffffu, rs, 8, 16);
            l_i[i] = l_i[i] * ef + rs;
            #pragma unroll
            for (int j = 0; j < 8; j++) acc[i][j] *= ef;
        }

        // stage P
        #pragma unroll
        for (int i = 0; i < 4; i++)
            #pragma unroll
            for (int j = 0; j < 4; j++)
                Ps[(ty4 + i) * 68 + tx4 + j] = sa[i][j];
        __syncthreads();   // K reads done, P staged -> reload KV as V

        // Load V tile (64 x 128), natural layout, into KV[r][e]
        {
            int row = tid >> 5;
            int c4  = (tid & 31) * 4;
            #pragma unroll
            for (int it = 0; it < 8; ++it) {
                int r = row + it * 8;
                float4 v = *(const float4*)(Vg + (k0t + r) * DHEAD + c4);
                *(float4*)&KV[r * 132 + c4] = v;
            }
        }
        __syncthreads();

        // O += P @ V
        #pragma unroll 4
        for (int k = 0; k < 64; k++) {
            float4 v0 = *(float4*)&KV[k * 132 + tx8];
            float4 v1 = *(float4*)&KV[k * 132 + tx8 + 4];
            #pragma unroll
            for (int i = 0; i < 4; i++) {
                float p = Ps[(ty4 + i) * 68 + k];
                acc[i][0] = fmaf(p, v0.x, acc[i][0]);
                acc[i][1] = fmaf(p, v0.y, acc[i][1]);
                acc[i][2] = fmaf(p, v0.z, acc[i][2]);
                acc[i][3] = fmaf(p, v0.w, acc[i][3]);
                acc[i][4] = fmaf(p, v1.x, acc[i][4]);
                acc[i][5] = fmaf(p, v1.y, acc[i][5]);
                acc[i][6] = fmaf(p, v1.z, acc[i][6]);
                acc[i][7] = fmaf(p, v1.w, acc[i][7]);
            }
        }
    }

    // normalize + write Z in [B][S][H][Dh]
    #pragma unroll
    for (int i = 0; i < 4; i++) {
        int qg = q0 + ty4 + i;
        float inv = 1.0f / l_i[i];
        float* zr = g_Z + ((size_t)(b * SEQ + qg) * NHEADS + h) * DHEAD + tx8;
        #pragma unroll
        for (int j = 0; j < 8; j++) zr[j] = acc[i][j] * inv;
    }
}

// ---------------------------------------------------------------------------
// Phase 3: output projection.  out[m][n] = Z[m][:] . WO_flat[:][n] + bO[n]
// WO[h][e][d] flattens exactly to row-major [2048][2048] over k = h*128+e.
// ---------------------------------------------------------------------------
__global__ __launch_bounds__(256) void out_gemm_kernel(
    const float* __restrict__ WO, const float* __restrict__ bO,
    float* __restrict__ out)
{
    __shared__ float As[16][132];
    __shared__ float Bs[16][132];

    const int n0  = blockIdx.x * 128;
    const int m0  = blockIdx.y * 128;
    const int tid = threadIdx.x;
    const int txc = tid & 15, tyr = tid >> 4;

    float acc[8][8];
    #pragma unroll
    for (int i = 0; i < 8; i++)
        #pragma unroll
        for (int j = 0; j < 8; j++) acc[i][j] = 0.f;

    for (int k0 = 0; k0 < DMODEL; k0 += 16) {
        #pragma unroll
        for (int it = 0; it < 2; ++it) {
            int t  = tid + it * 256;
            int ar = t >> 2;
            int ac = (t & 3) * 4;
            float4 v = *(const float4*)(g_Z + (size_t)(m0 + ar) * DMODEL + k0 + ac);
            As[ac + 0][ar] = v.x; As[ac + 1][ar] = v.y;
            As[ac + 2][ar] = v.z; As[ac + 3][ar] = v.w;
        }
        #pragma unroll
        for (int it = 0; it < 2; ++it) {
            int t  = tid + it * 256;
            int br = t >> 5;
            int bc = (t & 31) * 4;
            *(float4*)&Bs[br][bc] = *(const float4*)(WO + (size_t)(k0 + br) * DMODEL + n0 + bc);
        }
        __syncthreads();

        #pragma unroll
        for (int k = 0; k < 16; k++) {
            float ra[8], rb[8];
            *(float4*)(ra)     = *(float4*)&As[k][tyr * 8];
            *(float4*)(ra + 4) = *(float4*)&As[k][tyr * 8 + 4];
            *(float4*)(rb)     = *(float4*)&Bs[k][txc * 8];
            *(float4*)(rb + 4) = *(float4*)&Bs[k][txc * 8 + 4];
            #pragma unroll
            for (int i = 0; i < 8; i++)
                #pragma unroll
                for (int j = 0; j < 8; j++)
                    acc[i][j] = fmaf(ra[i], rb[j], acc[i][j]);
        }
        __syncthreads();
    }

    #pragma unroll
    for (int i = 0; i < 8; i++) {
        int m = m0 + tyr * 8 + i;
        float*       orow = out + (size_t)m * DMODEL + n0 + txc * 8;
        const float* brow = bO + n0 + txc * 8;
        #pragma unroll
        for (int j = 0; j < 8; j++) orow[j] = acc[i][j] + brow[j];
    }
}

// ---------------------------------------------------------------------------
extern "C" void kernel_launch(void* const* d_in, const int* in_sizes, int n_in,
                              void* d_out, int out_size)
{
    const float* x  = (const float*)d_in[0];
    const float* Wq = (const float*)d_in[1];
    const float* Wk = (const float*)d_in[2];
    const float* Wv = (const float*)d_in[3];
    const float* Wo = (const float*)d_in[4];
    const float* bq = (const float*)d_in[5];
    const float* bk = (const float*)d_in[6];
    const float* bv = (const float*)d_in[7];
    const float* bo = (const float*)d_in[8];
    float* out = (float*)d_out;

    dim3 blk(256);

    // Phase 1: QKV projections (fused launch, z = Q/K/V)
    qkv_gemm_kernel<<<dim3(16, 32, 3), blk>>>(x, Wq, Wk, Wv, bq, bk, bv);

    // Phase 2: causal flash attention
    cudaFuncSetAttribute(attn_kernel, cudaFuncAttributeMaxDynamicSharedMemorySize,
                         ATTN_SMEM_BYTES);
    attn_kernel<<<dim3(32, 32), blk, ATTN_SMEM_BYTES>>>();

    // Phase 3: output projection
    out_gemm_kernel<<<dim3(16, 32), blk>>>(Wo, bo, out);
}

// round 2
// speedup vs baseline: 3.4820x; 3.4820x over previous
#include <cuda_runtime.h>
#include <math.h>

#define BATCH   2
#define SEQ     2048
#define DMODEL  2048
#define NHEADS  16
#define DHEAD   128

// Scratch (allocation-free: __device__ globals)
__device__ float g_Q[BATCH*NHEADS*SEQ*DHEAD];   // [B][H][S][Dh]
__device__ float g_K[BATCH*NHEADS*SEQ*DHEAD];
__device__ float g_V[BATCH*NHEADS*SEQ*DHEAD];
__device__ float g_Z[BATCH*SEQ*NHEADS*DHEAD];   // [B][S][H][Dh]

// ---------------------------------------------------------------------------
// tf32 helpers
// ---------------------------------------------------------------------------
__device__ __forceinline__ unsigned f2tf32(float x) {
    unsigned y;
    asm("cvt.rna.tf32.f32 %0, %1;" : "=r"(y) : "f"(x));
    return y;
}

__device__ __forceinline__ void mma_tf32(float* c, const unsigned* a, const unsigned* b) {
    asm volatile(
        "mma.sync.aligned.m16n8k8.row.col.f32.tf32.tf32.f32 "
        "{%0,%1,%2,%3}, {%4,%5,%6,%7}, {%8,%9}, {%0,%1,%2,%3};\n"
        : "+f"(c[0]), "+f"(c[1]), "+f"(c[2]), "+f"(c[3])
        : "r"(a[0]), "r"(a[1]), "r"(a[2]), "r"(a[3]), "r"(b[0]), "r"(b[1]));
}

// ---------------------------------------------------------------------------
// Phase 1: QKV projection (tf32 tensor cores).
// grid = (16 heads, 32 m-tiles, 3 {Q,K,V}), block tile 128x128, ktile 32.
// 8 warps: warpM in {0,1} (64 rows), warpN in {0..3} (32 cols).
// ---------------------------------------------------------------------------
__global__ __launch_bounds__(256) void qkv_gemm_tc(
    const float* __restrict__ X,
    const float* __restrict__ Wq, const float* __restrict__ Wk, const float* __restrict__ Wv,
    const float* __restrict__ bq, const float* __restrict__ bk, const float* __restrict__ bv)
{
    __shared__ unsigned As[128][36];   // [m][k] tf32
    __shared__ unsigned Bs[32][136];   // [k][n] tf32

    const float* W; const float* bias; float* out;
    if (blockIdx.z == 0)      { W = Wq; bias = bq; out = g_Q; }
    else if (blockIdx.z == 1) { W = Wk; bias = bk; out = g_K; }
    else                      { W = Wv; bias = bv; out = g_V; }

    const int h   = blockIdx.x;
    const int m0  = blockIdx.y * 128;
    const int tid = threadIdx.x;
    const int warp = tid >> 5, lane = tid & 31;
    const int warpM = warp >> 2, warpN = warp & 3;
    const int lq = lane >> 2, lr = lane & 3;   // groupID, threadID_in_group
    const float* Wh = W + (size_t)h * DMODEL * DHEAD;

    float c[4][4][4];
    #pragma unroll
    for (int mi = 0; mi < 4; mi++)
        #pragma unroll
        for (int ni = 0; ni < 4; ni++)
            #pragma unroll
            for (int j = 0; j < 4; j++) c[mi][ni][j] = 0.f;

    for (int k0 = 0; k0 < DMODEL; k0 += 32) {
        __syncthreads();
        // stage A: 128 x 32 (8 float4 per row)
        #pragma unroll
        for (int i = 0; i < 4; i++) {
            int idx = tid + i * 256;
            int row = idx >> 3, col = (idx & 7) * 4;
            float4 v = *(const float4*)(X + (size_t)(m0 + row) * DMODEL + k0 + col);
            As[row][col + 0] = f2tf32(v.x); As[row][col + 1] = f2tf32(v.y);
            As[row][col + 2] = f2tf32(v.z); As[row][col + 3] = f2tf32(v.w);
        }
        // stage B: 32 x 128
        #pragma unroll
        for (int i = 0; i < 4; i++) {
            int idx = tid + i * 256;
            int row = idx >> 5, col = (idx & 31) * 4;
            float4 v = *(const float4*)(Wh + (size_t)(k0 + row) * DHEAD + col);
            Bs[row][col + 0] = f2tf32(v.x); Bs[row][col + 1] = f2tf32(v.y);
            Bs[row][col + 2] = f2tf32(v.z); Bs[row][col + 3] = f2tf32(v.w);
        }
        __syncthreads();

        #pragma unroll
        for (int kk = 0; kk < 32; kk += 8) {
            unsigned a[4][4], b[4][2];
            const int kc = kk + lr;
            #pragma unroll
            for (int mi = 0; mi < 4; mi++) {
                int r = warpM * 64 + mi * 16 + lq;
                a[mi][0] = As[r][kc];     a[mi][1] = As[r + 8][kc];
                a[mi][2] = As[r][kc + 4]; a[mi][3] = As[r + 8][kc + 4];
            }
            #pragma unroll
            for (int ni = 0; ni < 4; ni++) {
                int nb = warpN * 32 + ni * 8 + lq;
                b[ni][0] = Bs[kc][nb]; b[ni][1] = Bs[kc + 4][nb];
            }
            #pragma unroll
            for (int mi = 0; mi < 4; mi++)
                #pragma unroll
                for (int ni = 0; ni < 4; ni++)
                    mma_tf32(c[mi][ni], a[mi], b[ni]);
        }
    }

    // epilogue
    #pragma unroll
    for (int mi = 0; mi < 4; mi++) {
        #pragma unroll
        for (int half = 0; half < 2; half++) {
            int m = m0 + warpM * 64 + mi * 16 + lq + half * 8;
            int b_ = m >> 11, s = m & 2047;
            float* orow = out + (((size_t)(b_ * NHEADS + h)) * SEQ + s) * DHEAD;
            #pragma unroll
            for (int ni = 0; ni < 4; ni++) {
                int n = warpN * 32 + ni * 8 + 2 * lr;
                float2 r;
                r.x = c[mi][ni][half * 2 + 0] + bias[h * DHEAD + n];
                r.y = c[mi][ni][half * 2 + 1] + bias[h * DHEAD + n + 1];
                *(float2*)(orow + n) = r;
            }
        }
    }
}

// ---------------------------------------------------------------------------
// Phase 2: causal flash attention (tf32 tensor cores).
// grid = (32 q-tiles, B*H), 256 threads = 8 warps: warpR in {0..3} (16 rows),
// warpC in {0,1} (S: 32 cols, O: 64 cols). q-tile 64, kv-tile 64.
// ---------------------------------------------------------------------------
#define QP 132
#define KP 132
#define VP 136
#define PP 68
#define AOFF_KV (64*QP)            // 8448
#define AOFF_P  (AOFF_KV + 64*VP)  // 17152
#define AOFF_MX (AOFF_P + 64*PP)   // 21504
#define AOFF_SM (AOFF_MX + 128)    // 21632
#define ATT_SMEM_BYTES ((AOFF_SM + 128) * 4)   // 87040

__global__ __launch_bounds__(256, 2) void attn_tc()
{
    extern __shared__ unsigned smu[];
    unsigned* Qs  = smu;             // [64][QP]
    unsigned* KVs = smu + AOFF_KV;   // K: [64][KP] row=key, col=dh / V: [64][VP] row=key, col=e
    unsigned* Ps  = smu + AOFF_P;    // [64][PP]
    float* smax = (float*)(smu + AOFF_MX);   // [2][64]
    float* ssum = (float*)(smu + AOFF_SM);   // [2][64]

    const int tid = threadIdx.x;
    const int warp = tid >> 5, lane = tid & 31;
    const int warpR = warp >> 1, warpC = warp & 1;
    const int lq = lane >> 2, lr = lane & 3;
    const int bh = blockIdx.y;
    const int b  = bh >> 4, h = bh & 15;
    const int q0 = blockIdx.x * 64;
    const int r_loc = warpR * 16 + lq;

    const float* Qg = g_Q + (size_t)(b * NHEADS + h) * SEQ * DHEAD;
    const float* Kg = g_K + (size_t)(b * NHEADS + h) * SEQ * DHEAD;
    const float* Vg = g_V + (size_t)(b * NHEADS + h) * SEQ * DHEAD;

    const float scale = 0.08838834764831845f;  // 1/sqrt(128), folded into Q

    // load Q tile 64x128, scaled, as tf32
    #pragma unroll
    for (int i = 0; i < 8; i++) {
        int idx = tid + i * 256;
        int row = idx >> 5, col = (idx & 31) * 4;
        float4 v = *(const float4*)(Qg + (size_t)(q0 + row) * DHEAD + col);
        Qs[row * QP + col + 0] = f2tf32(v.x * scale);
        Qs[row * QP + col + 1] = f2tf32(v.y * scale);
        Qs[row * QP + col + 2] = f2tf32(v.z * scale);
        Qs[row * QP + col + 3] = f2tf32(v.w * scale);
    }

    float o[8][4];
    #pragma unroll
    for (int ni = 0; ni < 8; ni++)
        #pragma unroll
        for (int j = 0; j < 4; j++) o[ni][j] = 0.f;
    float m0v = -INFINITY, m1v = -INFINITY, l0 = 0.f, l1 = 0.f;

    const int ntiles = blockIdx.x + 1;   // causal tile skipping

    for (int kt = 0; kt < ntiles; kt++) {
        const int k0t = kt * 64;
        __syncthreads();   // prev PV done with KVs; Q visible on first iter
        // load K tile 64x128 -> KVs[key][dh]
        #pragma unroll
        for (int i = 0; i < 8; i++) {
            int idx = tid + i * 256;
            int row = idx >> 5, col = (idx & 31) * 4;
            float4 v = *(const float4*)(Kg + (size_t)(k0t + row) * DHEAD + col);
            KVs[row * KP + col + 0] = f2tf32(v.x);
            KVs[row * KP + col + 1] = f2tf32(v.y);
            KVs[row * KP + col + 2] = f2tf32(v.z);
            KVs[row * KP + col + 3] = f2tf32(v.w);
        }
        __syncthreads();

        // S = Q K^T : warp computes 16 x 32 (4 n8 tiles), k = 128
        float s[4][4];
        #pragma unroll
        for (int ni = 0; ni < 4; ni++)
            #pragma unroll
            for (int j = 0; j < 4; j++) s[ni][j] = 0.f;

        #pragma unroll
        for (int kk = 0; kk < 128; kk += 8) {
            unsigned aq[4], bb[2];
            const int kc = kk + lr;
            aq[0] = Qs[r_loc * QP + kc];       aq[1] = Qs[(r_loc + 8) * QP + kc];
            aq[2] = Qs[r_loc * QP + kc + 4];   aq[3] = Qs[(r_loc + 8) * QP + kc + 4];
            #pragma unroll
            for (int ni = 0; ni < 4; ni++) {
                int nb = warpC * 32 + ni * 8 + lq;
                bb[0] = KVs[nb * KP + kc];
                bb[1] = KVs[nb * KP + kc + 4];
                mma_tf32(s[ni], aq, bb);
            }
        }

        // causal mask + per-thread row max
        const int r0g = q0 + r_loc, r1g = r0g + 8;
        float mx0 = -1e30f, mx1 = -1e30f;
        #pragma unroll
        for (int ni = 0; ni < 4; ni++) {
            int cb = k0t + warpC * 32 + ni * 8 + 2 * lr;
            if (cb     > r0g) s[ni][0] = -1e30f;
            if (cb + 1 > r0g) s[ni][1] = -1e30f;
            if (cb     > r1g) s[ni][2] = -1e30f;
            if (cb + 1 > r1g) s[ni][3] = -1e30f;
            mx0 = fmaxf(mx0, fmaxf(s[ni][0], s[ni][1]));
            mx1 = fmaxf(mx1, fmaxf(s[ni][2], s[ni][3]));
        }
        mx0 = fmaxf(mx0, __shfl_xor_sync(0xffffffffu, mx0, 1));
        mx0 = fmaxf(mx0, __shfl_xor_sync(0xffffffffu, mx0, 2));
        mx1 = fmaxf(mx1, __shfl_xor_sync(0xffffffffu, mx1, 1));
        mx1 = fmaxf(mx1, __shfl_xor_sync(0xffffffffu, mx1, 2));
        if (lr == 0) {
            smax[warpC * 64 + r_loc]     = mx0;
            smax[warpC * 64 + r_loc + 8] = mx1;
        }
        __syncthreads();   // all warps done with K reads too
        mx0 = fmaxf(mx0, smax[(warpC ^ 1) * 64 + r_loc]);
        mx1 = fmaxf(mx1, smax[(warpC ^ 1) * 64 + r_loc + 8]);

        float mn0 = fmaxf(m0v, mx0), mn1 = fmaxf(m1v, mx1);
        float ef0 = __expf(m0v - mn0), ef1 = __expf(m1v - mn1);
        m0v = mn0; m1v = mn1;

        float sum0 = 0.f, sum1 = 0.f;
        #pragma unroll
        for (int ni = 0; ni < 4; ni++) {
            float p0 = __expf(s[ni][0] - mn0);
            float p1 = __expf(s[ni][1] - mn0);
            float p2 = __expf(s[ni][2] - mn1);
            float p3 = __expf(s[ni][3] - mn1);
            sum0 += p0 + p1; sum1 += p2 + p3;
            int kc2 = warpC * 32 + ni * 8 + 2 * lr;
            Ps[r_loc * PP + kc2]           = f2tf32(p0);
            Ps[r_loc * PP + kc2 + 1]       = f2tf32(p1);
            Ps[(r_loc + 8) * PP + kc2]     = f2tf32(p2);
            Ps[(r_loc + 8) * PP + kc2 + 1] = f2tf32(p3);
        }
        sum0 += __shfl_xor_sync(0xffffffffu, sum0, 1);
        sum0 += __shfl_xor_sync(0xffffffffu, sum0, 2);
        sum1 += __shfl_xor_sync(0xffffffffu, sum1, 1);
        sum1 += __shfl_xor_sync(0xffffffffu, sum1, 2);
        if (lr == 0) {
            ssum[warpC * 64 + r_loc]     = sum0;
            ssum[warpC * 64 + r_loc + 8] = sum1;
        }
        // rescale O accumulator
        #pragma unroll
        for (int ni = 0; ni < 8; ni++) {
            o[ni][0] *= ef0; o[ni][1] *= ef0;
            o[ni][2] *= ef1; o[ni][3] *= ef1;
        }
        // load V tile 64x128 -> KVs[key][e] (K reads finished before last sync)
        #pragma unroll
        for (int i = 0; i < 8; i++) {
            int idx = tid + i * 256;
            int row = idx >> 5, col = (idx & 31) * 4;
            float4 v = *(const float4*)(Vg + (size_t)(k0t + row) * DHEAD + col);
            KVs[row * VP + col + 0] = f2tf32(v.x);
            KVs[row * VP + col + 1] = f2tf32(v.y);
            KVs[row * VP + col + 2] = f2tf32(v.z);
            KVs[row * VP + col + 3] = f2tf32(v.w);
        }
        __syncthreads();   // Ps + V + ssum visible

        l0 = l0 * ef0 + sum0 + ssum[(warpC ^ 1) * 64 + r_loc];
        l1 = l1 * ef1 + sum1 + ssum[(warpC ^ 1) * 64 + r_loc + 8];

        // O += P @ V : warp computes 16 x 64 (8 n8 tiles), k = 64
        #pragma unroll
        for (int kk = 0; kk < 64; kk += 8) {
            unsigned ap[4], bb[2];
            const int kc = kk + lr;
            ap[0] = Ps[r_loc * PP + kc];       ap[1] = Ps[(r_loc + 8) * PP + kc];
            ap[2] = Ps[r_loc * PP + kc + 4];   ap[3] = Ps[(r_loc + 8) * PP + kc + 4];
            #pragma unroll
            for (int ni = 0; ni < 8; ni++) {
                int nb = warpC * 64 + ni * 8 + lq;
                bb[0] = KVs[kc * VP + nb];
                bb[1] = KVs[(kc + 4) * VP + nb];
                mma_tf32(o[ni], ap, bb);
            }
        }
    }

    // normalize + write Z in [B][S][H][Dh]
    float inv0 = 1.f / l0, inv1 = 1.f / l1;
    const int q_0 = q0 + r_loc;
    #pragma unroll
    for (int ni = 0; ni < 8; ni++) {
        int e = warpC * 64 + ni * 8 + 2 * lr;
        float2 z0; z0.x = o[ni][0] * inv0; z0.y = o[ni][1] * inv0;
        float2 z1; z1.x = o[ni][2] * inv1; z1.y = o[ni][3] * inv1;
        *(float2*)(g_Z + (((size_t)(b * SEQ + q_0)) * NHEADS + h) * DHEAD + e)     = z0;
        *(float2*)(g_Z + (((size_t)(b * SEQ + q_0 + 8)) * NHEADS + h) * DHEAD + e) = z1;
    }
}

// ---------------------------------------------------------------------------
// Phase 3: output projection (tf32 tensor cores). M=4096, N=2048, K=2048.
// grid = (16 n-tiles, 32 m-tiles), block tile 128x128.
// ---------------------------------------------------------------------------
__global__ __launch_bounds__(256) void out_gemm_tc(
    const float* __restrict__ WO, const float* __restrict__ bO,
    float* __restrict__ out)
{
    __shared__ unsigned As[128][36];
    __shared__ unsigned Bs[32][136];

    const int n0  = blockIdx.x * 128;
    const int m0  = blockIdx.y * 128;
    const int tid = threadIdx.x;
    const int warp = tid >> 5, lane = tid & 31;
    const int warpM = warp >> 2, warpN = warp & 3;
    const int lq = lane >> 2, lr = lane & 3;

    float c[4][4][4];
    #pragma unroll
    for (int mi = 0; mi < 4; mi++)
        #pragma unroll
        for (int ni = 0; ni < 4; ni++)
            #pragma unroll
            for (int j = 0; j < 4; j++) c[mi][ni][j] = 0.f;

    for (int k0 = 0; k0 < DMODEL; k0 += 32) {
        __syncthreads();
        #pragma unroll
        for (int i = 0; i < 4; i++) {
            int idx = tid + i * 256;
            int row = idx >> 3, col = (idx & 7) * 4;
            float4 v = *(const float4*)(g_Z + (size_t)(m0 + row) * DMODEL + k0 + col);
            As[row][col + 0] = f2tf32(v.x); As[row][col + 1] = f2tf32(v.y);
            As[row][col + 2] = f2tf32(v.z); As[row][col + 3] = f2tf32(v.w);
        }
        #pragma unroll
        for (int i = 0; i < 4; i++) {
            int idx = tid + i * 256;
            int row = idx >> 5, col = (idx & 31) * 4;
            float4 v = *(const float4*)(WO + (size_t)(k0 + row) * DMODEL + n0 + col);
            Bs[row][col + 0] = f2tf32(v.x); Bs[row][col + 1] = f2tf32(v.y);
            Bs[row][col + 2] = f2tf32(v.z); Bs[row][col + 3] = f2tf32(v.w);
        }
        __syncthreads();

        #pragma unroll
        for (int kk = 0; kk < 32; kk += 8) {
            unsigned a[4][4], b[4][2];
            const int kc = kk + lr;
            #pragma unroll
            for (int mi = 0; mi < 4; mi++) {
                int r = warpM * 64 + mi * 16 + lq;
                a[mi][0] = As[r][kc];     a[mi][1] = As[r + 8][kc];
                a[mi][2] = As[r][kc + 4]; a[mi][3] = As[r + 8][kc + 4];
            }
            #pragma unroll
            for (int ni = 0; ni < 4; ni++) {
                int nb = warpN * 32 + ni * 8 + lq;
                b[ni][0] = Bs[kc][nb]; b[ni][1] = Bs[kc + 4][nb];
            }
            #pragma unroll
            for (int mi = 0; mi < 4; mi++)
                #pragma unroll
                for (int ni = 0; ni < 4; ni++)
                    mma_tf32(c[mi][ni], a[mi], b[ni]);
        }
    }

    #pragma unroll
    for (int mi = 0; mi < 4; mi++) {
        #pragma unroll
        for (int half = 0; half < 2; half++) {
            int m = m0 + warpM * 64 + mi * 16 + lq + half * 8;
            float* orow = out + (size_t)m * DMODEL + n0;
            #pragma unroll
            for (int ni = 0; ni < 4; ni++) {
                int n = warpN * 32 + ni * 8 + 2 * lr;
                float2 r;
                r.x = c[mi][ni][half * 2 + 0] + bO[n0 + n];
                r.y = c[mi][ni][half * 2 + 1] + bO[n0 + n + 1];
                *(float2*)(orow + n) = r;
            }
        }
    }
}

// ---------------------------------------------------------------------------
extern "C" void kernel_launch(void* const* d_in, const int* in_sizes, int n_in,
                              void* d_out, int out_size)
{
    const float* x  = (const float*)d_in[0];
    const float* Wq = (const float*)d_in[1];
    const float* Wk = (const float*)d_in[2];
    const float* Wv = (const float*)d_in[3];
    const float* Wo = (const float*)d_in[4];
    const float* bq = (const float*)d_in[5];
    const float* bk = (const float*)d_in[6];
    const float* bv = (const float*)d_in[7];
    const float* bo = (const float*)d_in[8];
    float* out = (float*)d_out;

    dim3 blk(256);

    qkv_gemm_tc<<<dim3(16, 32, 3), blk>>>(x, Wq, Wk, Wv, bq, bk, bv);

    cudaFuncSetAttribute(attn_tc, cudaFuncAttributeMaxDynamicSharedMemorySize,
                         ATT_SMEM_BYTES);
    attn_tc<<<dim3(32, 32), blk, ATT_SMEM_BYTES>>>();

    out_gemm_tc<<<dim3(16, 32), blk>>>(Wo, bo, out);
}